// round 11
// baseline (speedup 1.0000x reference)
#include <cuda_runtime.h>
#include <cuda_bf16.h>

// ---------------------------------------------------------------------------
// 2-layer GCN. CSR pull aggregation, tf32 tensor-core GEMMs.
// Tail (gather1+relu -> GEMM2 -> gather2) fused into ONE persistent kernel
// with software grid barriers (co-residency guaranteed by launch bounds).
// Chain B (zero/count/scan/fill) overlapped with GEMM1 on a forked stream.
// ---------------------------------------------------------------------------

#define NMAX   50048
#define EMAX   800000
#define INF    128
#define OUTF   64
#define SCB    512
#define NBLK   444        // 148 SMs x 3 co-resident blocks (launch bounds below)

__device__ int   g_cnt [NMAX];
__device__ int   g_ptr [NMAX + 1];
__device__ int   g_fill[NMAX];
__device__ volatile int g_ready[128];      // lookback scan flags
__device__ volatile unsigned g_bar_cnt;    // grid barrier (self-resetting)
__device__ volatile unsigned g_bar_gen;
__device__ int2  g_edge[EMAX];             // (src, coeff bits)
__device__ float g_dinv[NMAX];
__device__ float g_h1  [NMAX * INF];       // X @ W1
__device__ float g_act1[NMAX * INF];       // relu(A~ h1 + b1)
__device__ float g_h2  [NMAX * OUTF];      // act1 @ W2

// ---------------------------------------------------------------------------
__device__ __forceinline__ int block_probe_is64(const int* __restrict__ w32) {
    __shared__ int s_is64;
    if (threadIdx.x == 0) s_is64 = 1;
    __syncthreads();
    if (threadIdx.x < 256) {
        if (w32[2 * threadIdx.x + 1] != 0) s_is64 = 0;
    }
    __syncthreads();
    return s_is64;
}

__global__ void k_zero(int M, int NB) {
    int i = blockIdx.x * blockDim.x + threadIdx.x;
    if (i < M)  g_cnt[i] = 0;
    if (i < NB) g_ready[i] = 0;
}

// histogram of destinations, 4 edges per thread
__global__ void k_count(const void* __restrict__ ei, int E) {
    int is64 = block_probe_is64((const int*)ei);
    int i  = blockIdx.x * blockDim.x + threadIdx.x;
    int n4 = E >> 2;
    if (i < n4) {
        int base = 4 * i;
        int d0, d1, d2, d3;
        if (is64) {
            const long long* p = (const long long*)ei;
            if ((E & 1) == 0) {
                longlong2 a = *(const longlong2*)&p[E + base];
                longlong2 b = *(const longlong2*)&p[E + base + 2];
                d0 = (int)a.x; d1 = (int)a.y; d2 = (int)b.x; d3 = (int)b.y;
            } else {
                d0 = (int)p[E+base]; d1 = (int)p[E+base+1];
                d2 = (int)p[E+base+2]; d3 = (int)p[E+base+3];
            }
        } else {
            const int* p = (const int*)ei;
            if ((E & 3) == 0) {
                int4 v = *(const int4*)&p[E + base];
                d0 = v.x; d1 = v.y; d2 = v.z; d3 = v.w;
            } else {
                d0 = p[E+base]; d1 = p[E+base+1]; d2 = p[E+base+2]; d3 = p[E+base+3];
            }
        }
        atomicAdd(&g_cnt[d0], 1); atomicAdd(&g_cnt[d1], 1);
        atomicAdd(&g_cnt[d2], 1); atomicAdd(&g_cnt[d3], 1);
    } else if (i == n4) {
        for (int e = 4 * n4; e < E; e++) {
            int d = is64 ? (int)((const long long*)ei)[E + e] : ((const int*)ei)[E + e];
            atomicAdd(&g_cnt[d], 1);
        }
    }
}

// single-wave decoupled-lookback exclusive scan + dinv
__global__ void k_scan_lb(int M) {
    __shared__ int sh[SCB];
    __shared__ int s_off;
    const int t = threadIdx.x;
    const int b = blockIdx.x;
    const int node = b * SCB + t;

    int c = (node < M) ? g_cnt[node] : 0;
    if (node < M) g_dinv[node] = rsqrtf((float)(c + 1));

    sh[t] = c;
    __syncthreads();
    for (int o = 1; o < SCB; o <<= 1) {
        int u = (t >= o) ? sh[t - o] : 0;
        __syncthreads();
        sh[t] += u;
        __syncthreads();
    }
    int incl  = sh[t];
    int total = sh[SCB - 1];

    if (t == 0) {
        s_off = 0;
        g_ready[b] = total + 1;
    }
    __syncthreads();
    if (t < b) {
        int v;
        while ((v = g_ready[t]) == 0) { }
        atomicAdd(&s_off, v - 1);
    }
    __syncthreads();

    int off = s_off;
    if (node < M) {
        int excl = off + incl - c;
        g_ptr[node]  = excl;
        g_fill[node] = excl;
        if (node == M - 1) g_ptr[M] = off + incl;
    }
}

// fill CSR, 4 edges per thread
__global__ void k_fillcsr(const void* __restrict__ ei, int E) {
    int is64 = block_probe_is64((const int*)ei);
    int i  = blockIdx.x * blockDim.x + threadIdx.x;
    int n4 = E >> 2;
    if (i < n4) {
        int base = 4 * i;
        int s0,s1,s2,s3,d0,d1,d2,d3;
        if (is64) {
            const long long* p = (const long long*)ei;
            longlong2 sa = *(const longlong2*)&p[base];
            longlong2 sb = *(const longlong2*)&p[base + 2];
            s0=(int)sa.x; s1=(int)sa.y; s2=(int)sb.x; s3=(int)sb.y;
            if ((E & 1) == 0) {
                longlong2 da = *(const longlong2*)&p[E + base];
                longlong2 db = *(const longlong2*)&p[E + base + 2];
                d0=(int)da.x; d1=(int)da.y; d2=(int)db.x; d3=(int)db.y;
            } else {
                d0=(int)p[E+base]; d1=(int)p[E+base+1];
                d2=(int)p[E+base+2]; d3=(int)p[E+base+3];
            }
        } else {
            const int* p = (const int*)ei;
            int4 sv = *(const int4*)&p[base];
            s0=sv.x; s1=sv.y; s2=sv.z; s3=sv.w;
            if ((E & 3) == 0) {
                int4 dv = *(const int4*)&p[E + base];
                d0=dv.x; d1=dv.y; d2=dv.z; d3=dv.w;
            } else {
                d0=p[E+base]; d1=p[E+base+1]; d2=p[E+base+2]; d3=p[E+base+3];
            }
        }
        float c0 = g_dinv[s0]*g_dinv[d0], c1 = g_dinv[s1]*g_dinv[d1];
        float c2 = g_dinv[s2]*g_dinv[d2], c3 = g_dinv[s3]*g_dinv[d3];
        int p0 = atomicAdd(&g_fill[d0], 1); g_edge[p0] = make_int2(s0, __float_as_int(c0));
        int p1 = atomicAdd(&g_fill[d1], 1); g_edge[p1] = make_int2(s1, __float_as_int(c1));
        int p2 = atomicAdd(&g_fill[d2], 1); g_edge[p2] = make_int2(s2, __float_as_int(c2));
        int p3 = atomicAdd(&g_fill[d3], 1); g_edge[p3] = make_int2(s3, __float_as_int(c3));
    } else if (i == n4) {
        for (int e = 4 * n4; e < E; e++) {
            int s, d;
            if (is64) { const long long* p = (const long long*)ei; s=(int)p[e]; d=(int)p[E+e]; }
            else      { const int* p = (const int*)ei;             s=p[e];      d=p[E+e]; }
            float c = g_dinv[s] * g_dinv[d];
            int pos = atomicAdd(&g_fill[d], 1);
            g_edge[pos] = make_int2(s, __float_as_int(c));
        }
    }
}

// ---------------------------------------------------------------------------
__device__ __forceinline__ unsigned f2tf(float f) {
    unsigned r;
    asm("cvt.rna.tf32.f32 %0, %1;" : "=r"(r) : "f"(f));
    return r;
}

// GEMM1: g_h1 = X @ W1  (128 threads, 64-row tile, tf32 MMA)
__global__ void k_gemm1(const float* __restrict__ X, const float* __restrict__ W, int M)
{
    constexpr int PAD = 36;
    __shared__ unsigned xs[64 * PAD];
    __shared__ unsigned wt[128 * PAD];

    const int tid  = threadIdx.x;
    const int lane = tid & 31;
    const int wid  = tid >> 5;
    const int m0   = blockIdx.x * 64;
    const int mw   = wid * 16;

    float acc[16][4];
#pragma unroll
    for (int t = 0; t < 16; t++) { acc[t][0]=acc[t][1]=acc[t][2]=acc[t][3]=0.f; }

    const int r4 = lane >> 2;
    const int c4 = lane & 3;

    for (int kc = 0; kc < 128; kc += 32) {
#pragma unroll
        for (int i = 0; i < 4; i++) {
            int idx = tid + i * 128;
            int r   = idx >> 3;
            int kv  = (idx & 7) * 4;
            int row = m0 + r;
            float4 v = make_float4(0.f, 0.f, 0.f, 0.f);
            if (row < M) v = *(const float4*)&X[row * 128 + kc + kv];
            uint4 u = make_uint4(f2tf(v.x), f2tf(v.y), f2tf(v.z), f2tf(v.w));
            *(uint4*)&xs[r * PAD + kv] = u;
        }
#pragma unroll
        for (int i = 0; i < 8; i++) {
            int idx = tid + i * 128;          // over 32*128/4 = 1024
            int kk  = idx >> 5;
            int n4  = (idx & 31) * 4;
            float4 v = *(const float4*)&W[(kc + kk) * 128 + n4];
            wt[(n4 + 0) * PAD + kk] = f2tf(v.x);
            wt[(n4 + 1) * PAD + kk] = f2tf(v.y);
            wt[(n4 + 2) * PAD + kk] = f2tf(v.z);
            wt[(n4 + 3) * PAD + kk] = f2tf(v.w);
        }
        __syncthreads();

#pragma unroll
        for (int k0 = 0; k0 < 32; k0 += 8) {
            unsigned a0 = xs[(mw + r4    ) * PAD + k0 + c4    ];
            unsigned a1 = xs[(mw + r4 + 8) * PAD + k0 + c4    ];
            unsigned a2 = xs[(mw + r4    ) * PAD + k0 + c4 + 4];
            unsigned a3 = xs[(mw + r4 + 8) * PAD + k0 + c4 + 4];
#pragma unroll
            for (int nt = 0; nt < 16; nt++) {
                unsigned b0 = wt[(nt * 8 + r4) * PAD + k0 + c4    ];
                unsigned b1 = wt[(nt * 8 + r4) * PAD + k0 + c4 + 4];
                asm volatile(
                    "mma.sync.aligned.m16n8k8.row.col.f32.tf32.tf32.f32 "
                    "{%0,%1,%2,%3}, {%4,%5,%6,%7}, {%8,%9}, {%0,%1,%2,%3};"
                    : "+f"(acc[nt][0]), "+f"(acc[nt][1]),
                      "+f"(acc[nt][2]), "+f"(acc[nt][3])
                    : "r"(a0), "r"(a1), "r"(a2), "r"(a3), "r"(b0), "r"(b1));
            }
        }
        __syncthreads();
    }

    const int colb = c4 * 2;
    const int rowa = m0 + mw + r4;
#pragma unroll
    for (int nt = 0; nt < 16; nt++) {
        int n0 = nt * 8 + colb;
        if (rowa < M)
            *(float2*)&g_h1[rowa * 128 + n0] = make_float2(acc[nt][0], acc[nt][1]);
        if (rowa + 8 < M)
            *(float2*)&g_h1[(rowa + 8) * 128 + n0] = make_float2(acc[nt][2], acc[nt][3]);
    }
}

// ---------------------------------------------------------------------------
// software grid barrier (all blocks co-resident by construction)
// ---------------------------------------------------------------------------
__device__ __forceinline__ void grid_barrier() {
    __threadfence();
    __syncthreads();
    if (threadIdx.x == 0) {
        unsigned gen = g_bar_gen;
        unsigned t = atomicInc((unsigned*)&g_bar_cnt, gridDim.x - 1);
        if (t == gridDim.x - 1) {
            __threadfence();
            g_bar_gen = gen + 1;
        } else {
            while (g_bar_gen == gen) { }
        }
    }
    __syncthreads();
}

// ---------------------------------------------------------------------------
// fused tail: gather128(+b1,relu) -> GEMM2 -> gather64(+b2)
// ---------------------------------------------------------------------------
__global__ void __launch_bounds__(256, 3)
k_tail(const float* __restrict__ W2, const float* __restrict__ b1,
       const float* __restrict__ b2, float* __restrict__ outp, int M)
{
    constexpr int PAD = 36;
    __shared__ unsigned xs[128 * PAD];   // GEMM2 act tile (128 x 32)
    __shared__ unsigned wt[64 * PAD];    // GEMM2 W chunk transposed

    const int tid  = threadIdx.x;
    const int lane = tid & 31;
    const int wid  = tid >> 5;
    const int gw0  = blockIdx.x * 8 + wid;
    const int nwrp = gridDim.x * 8;

    // ---- phase 1: act1 = relu(A~ h1 + b1), one warp per node (grid-stride)
    {
        const float4* __restrict__ H = (const float4*)g_h1;
        const float4 bb = ((const float4*)b1)[lane];
        for (int w = gw0; w < M; w += nwrp) {
            int beg = g_ptr[w], end = g_ptr[w + 1];
            float cs = g_dinv[w]; cs *= cs;
            float4 v = H[w * 32 + lane];
            float4 a0 = make_float4(v.x*cs, v.y*cs, v.z*cs, v.w*cs);
            float4 a1 = make_float4(0.f,0.f,0.f,0.f);
            float4 a2 = make_float4(0.f,0.f,0.f,0.f);
            float4 a3 = make_float4(0.f,0.f,0.f,0.f);
            int e = beg;
            for (; e + 4 <= end; e += 4) {
                int2 p0 = g_edge[e];     int2 p1 = g_edge[e + 1];
                int2 p2 = g_edge[e + 2]; int2 p3 = g_edge[e + 3];
                float c0 = __int_as_float(p0.y), c1 = __int_as_float(p1.y);
                float c2 = __int_as_float(p2.y), c3 = __int_as_float(p3.y);
                float4 v0 = H[p0.x * 32 + lane];
                float4 v1 = H[p1.x * 32 + lane];
                float4 v2 = H[p2.x * 32 + lane];
                float4 v3 = H[p3.x * 32 + lane];
                a0.x=fmaf(v0.x,c0,a0.x); a0.y=fmaf(v0.y,c0,a0.y);
                a0.z=fmaf(v0.z,c0,a0.z); a0.w=fmaf(v0.w,c0,a0.w);
                a1.x=fmaf(v1.x,c1,a1.x); a1.y=fmaf(v1.y,c1,a1.y);
                a1.z=fmaf(v1.z,c1,a1.z); a1.w=fmaf(v1.w,c1,a1.w);
                a2.x=fmaf(v2.x,c2,a2.x); a2.y=fmaf(v2.y,c2,a2.y);
                a2.z=fmaf(v2.z,c2,a2.z); a2.w=fmaf(v2.w,c2,a2.w);
                a3.x=fmaf(v3.x,c3,a3.x); a3.y=fmaf(v3.y,c3,a3.y);
                a3.z=fmaf(v3.z,c3,a3.z); a3.w=fmaf(v3.w,c3,a3.w);
            }
            for (; e < end; e++) {
                int2 p0 = g_edge[e];
                float c0 = __int_as_float(p0.y);
                float4 v0 = H[p0.x * 32 + lane];
                a0.x=fmaf(v0.x,c0,a0.x); a0.y=fmaf(v0.y,c0,a0.y);
                a0.z=fmaf(v0.z,c0,a0.z); a0.w=fmaf(v0.w,c0,a0.w);
            }
            a0.x += a1.x + a2.x + a3.x;  a0.y += a1.y + a2.y + a3.y;
            a0.z += a1.z + a2.z + a3.z;  a0.w += a1.w + a2.w + a3.w;
            a0.x = fmaxf(a0.x + bb.x, 0.f);
            a0.y = fmaxf(a0.y + bb.y, 0.f);
            a0.z = fmaxf(a0.z + bb.z, 0.f);
            a0.w = fmaxf(a0.w + bb.w, 0.f);
            ((float4*)g_act1)[w * 32 + lane] = a0;
        }
    }
    grid_barrier();

    // ---- phase 2: g_h2 = act1 @ W2 (128-row tiles, 8 warps, tf32)
    {
        const int r4 = lane >> 2;
        const int c4 = lane & 3;
        const int mw = wid * 16;
        const int tiles = (M + 127) / 128;
        for (int tile = blockIdx.x; tile < tiles; tile += gridDim.x) {
            const int m0 = tile * 128;
            float acc[8][4];
#pragma unroll
            for (int t = 0; t < 8; t++) { acc[t][0]=acc[t][1]=acc[t][2]=acc[t][3]=0.f; }

            for (int kc = 0; kc < 128; kc += 32) {
#pragma unroll
                for (int i = 0; i < 4; i++) {
                    int idx = tid + i * 256;          // 0..1023
                    int r   = idx >> 3;
                    int kv  = (idx & 7) * 4;
                    int row = m0 + r;
                    float4 v = make_float4(0.f,0.f,0.f,0.f);
                    if (row < M) v = *(const float4*)&g_act1[row * 128 + kc + kv];
                    uint4 u = make_uint4(f2tf(v.x), f2tf(v.y), f2tf(v.z), f2tf(v.w));
                    *(uint4*)&xs[r * PAD + kv] = u;
                }
#pragma unroll
                for (int i = 0; i < 2; i++) {
                    int idx = tid + i * 256;          // over 32*64/4 = 512
                    int kk  = idx >> 4;
                    int n4  = (idx & 15) * 4;
                    float4 v = *(const float4*)&W2[(kc + kk) * 64 + n4];
                    wt[(n4 + 0) * PAD + kk] = f2tf(v.x);
                    wt[(n4 + 1) * PAD + kk] = f2tf(v.y);
                    wt[(n4 + 2) * PAD + kk] = f2tf(v.z);
                    wt[(n4 + 3) * PAD + kk] = f2tf(v.w);
                }
                __syncthreads();

#pragma unroll
                for (int k0 = 0; k0 < 32; k0 += 8) {
                    unsigned a0 = xs[(mw + r4    ) * PAD + k0 + c4    ];
                    unsigned a1 = xs[(mw + r4 + 8) * PAD + k0 + c4    ];
                    unsigned a2 = xs[(mw + r4    ) * PAD + k0 + c4 + 4];
                    unsigned a3 = xs[(mw + r4 + 8) * PAD + k0 + c4 + 4];
#pragma unroll
                    for (int nt = 0; nt < 8; nt++) {
                        unsigned b0 = wt[(nt * 8 + r4) * PAD + k0 + c4    ];
                        unsigned b1r = wt[(nt * 8 + r4) * PAD + k0 + c4 + 4];
                        asm volatile(
                            "mma.sync.aligned.m16n8k8.row.col.f32.tf32.tf32.f32 "
                            "{%0,%1,%2,%3}, {%4,%5,%6,%7}, {%8,%9}, {%0,%1,%2,%3};"
                            : "+f"(acc[nt][0]), "+f"(acc[nt][1]),
                              "+f"(acc[nt][2]), "+f"(acc[nt][3])
                            : "r"(a0), "r"(a1), "r"(a2), "r"(a3), "r"(b0), "r"(b1r));
                    }
                }
                __syncthreads();
            }

            const int colb = c4 * 2;
            const int rowa = m0 + mw + r4;
#pragma unroll
            for (int nt = 0; nt < 8; nt++) {
                int n0 = nt * 8 + colb;
                if (rowa < M)
                    *(float2*)&g_h2[rowa * 64 + n0] = make_float2(acc[nt][0], acc[nt][1]);
                if (rowa + 8 < M)
                    *(float2*)&g_h2[(rowa + 8) * 64 + n0] = make_float2(acc[nt][2], acc[nt][3]);
            }
        }
    }
    grid_barrier();

    // ---- phase 3: out = A~ h2 + b2, one warp per node (grid-stride)
    {
        const float2* __restrict__ H = (const float2*)g_h2;
        const float2 bb = ((const float2*)b2)[lane];
        for (int w = gw0; w < M; w += nwrp) {
            int beg = g_ptr[w], end = g_ptr[w + 1];
            float cs = g_dinv[w]; cs *= cs;
            float2 v = H[w * 32 + lane];
            float2 a0 = make_float2(fmaf(v.x, cs, bb.x), fmaf(v.y, cs, bb.y));
            float2 a1 = make_float2(0.f, 0.f);
            float2 a2 = make_float2(0.f, 0.f);
            float2 a3 = make_float2(0.f, 0.f);
            int e = beg;
            for (; e + 4 <= end; e += 4) {
                int2 p0 = g_edge[e];     int2 p1 = g_edge[e + 1];
                int2 p2 = g_edge[e + 2]; int2 p3 = g_edge[e + 3];
                float c0 = __int_as_float(p0.y), c1 = __int_as_float(p1.y);
                float c2 = __int_as_float(p2.y), c3 = __int_as_float(p3.y);
                float2 v0 = H[p0.x * 32 + lane];
                float2 v1 = H[p1.x * 32 + lane];
                float2 v2 = H[p2.x * 32 + lane];
                float2 v3 = H[p3.x * 32 + lane];
                a0.x=fmaf(v0.x,c0,a0.x); a0.y=fmaf(v0.y,c0,a0.y);
                a1.x=fmaf(v1.x,c1,a1.x); a1.y=fmaf(v1.y,c1,a1.y);
                a2.x=fmaf(v2.x,c2,a2.x); a2.y=fmaf(v2.y,c2,a2.y);
                a3.x=fmaf(v3.x,c3,a3.x); a3.y=fmaf(v3.y,c3,a3.y);
            }
            for (; e < end; e++) {
                int2 p0 = g_edge[e];
                float c0 = __int_as_float(p0.y);
                float2 v0 = H[p0.x * 32 + lane];
                a0.x=fmaf(v0.x,c0,a0.x); a0.y=fmaf(v0.y,c0,a0.y);
            }
            a0.x += a1.x + a2.x + a3.x;
            a0.y += a1.y + a2.y + a3.y;
            ((float2*)outp)[w * 32 + lane] = a0;
        }
    }
}

// ---------------------------------------------------------------------------
extern "C" void kernel_launch(void* const* d_in, const int* in_sizes, int n_in,
                              void* d_out, int out_size)
{
    const float* x  = (const float*)d_in[0];
    const void*  ei = d_in[1];
    const float* W1 = (const float*)d_in[2];
    const float* b1 = (const float*)d_in[3];
    const float* W2 = (const float*)d_in[4];
    const float* b2 = (const float*)d_in[5];
    float*       out = (float*)d_out;

    const int M = in_sizes[0] / INF;   // 50000
    const int E = in_sizes[1] / 2;     // 800000

    const int T  = 256;
    const int NB = (M + SCB - 1) / SCB;
    const int E4 = (E >> 2) + 1;

    cudaStream_t s1;
    cudaStreamCreateWithFlags(&s1, cudaStreamNonBlocking);
    cudaEvent_t evFork, evJoin;
    cudaEventCreateWithFlags(&evFork, cudaEventDisableTiming);
    cudaEventCreateWithFlags(&evJoin, cudaEventDisableTiming);

    cudaEventRecord(evFork, 0);
    cudaStreamWaitEvent(s1, evFork, 0);

    // chain B (s1): zero -> count -> lookback-scan(+dinv) -> fill
    k_zero   <<<(M + T - 1) / T, T, 0, s1>>>(M, NB);
    k_count  <<<(E4 + T - 1) / T, T, 0, s1>>>(ei, E);
    k_scan_lb<<<NB, SCB, 0, s1>>>(M);
    k_fillcsr<<<(E4 + T - 1) / T, T, 0, s1>>>(ei, E);
    cudaEventRecord(evJoin, s1);

    // chain A (default stream): GEMM1
    k_gemm1<<<(M + 63) / 64, 128>>>(x, W1, M);

    cudaStreamWaitEvent(0, evJoin, 0);

    // fused tail: gather+relu -> GEMM2 -> gather+bias
    k_tail<<<NBLK, 256>>>(W2, b1, b2, out, M);
}

// round 14
// speedup vs baseline: 1.0272x; 1.0272x over previous
#include <cuda_runtime.h>
#include <cuda_bf16.h>

// ---------------------------------------------------------------------------
// 2-layer GCN. Compact CSR pull aggregation (precomputed coefficients),
// tf32 tensor-core GEMMs, single-wave decoupled-lookback scan.
// Self-resetting scratch state: no zeroing kernel (scan resets g_cnt for the
// next replay; fillcsr resets the lookback flags). Chain B overlapped with
// GEMM1 via event fork/join.
// ---------------------------------------------------------------------------

#define NMAX   50048
#define EMAX   800000
#define INF    128
#define OUTF   64
#define SCB    512

__device__ int   g_cnt [NMAX];          // zero at load; re-zeroed by k_scan_lb
__device__ int   g_ptr [NMAX + 1];
__device__ int   g_fill[NMAX];
__device__ volatile int g_ready[128];   // zero at load; re-zeroed by k_fillcsr
__device__ int2  g_edge[EMAX];          // (src, coeff bits)
__device__ float g_dinv[NMAX];
__device__ float g_h1  [NMAX * INF];
__device__ float g_agg1[NMAX * INF];
__device__ float g_h2  [NMAX * OUTF];

// ---------------------------------------------------------------------------
__device__ __forceinline__ int block_probe_is64(const int* __restrict__ w32) {
    __shared__ int s_is64;
    if (threadIdx.x == 0) s_is64 = 1;
    __syncthreads();
    if (threadIdx.x < 256) {
        if (w32[2 * threadIdx.x + 1] != 0) s_is64 = 0;
    }
    __syncthreads();
    return s_is64;
}

// histogram of destinations, 2 edges per thread
__global__ void k_count(const void* __restrict__ ei, int E) {
    int is64 = block_probe_is64((const int*)ei);
    int i  = blockIdx.x * blockDim.x + threadIdx.x;
    int n2 = E >> 1;
    if (is64) {
        const longlong2* p = (const longlong2*)((const long long*)ei + E);
        if (i < n2) {
            longlong2 v = p[i];
            atomicAdd(&g_cnt[(int)v.x], 1);
            atomicAdd(&g_cnt[(int)v.y], 1);
        }
        if (i == 0 && (E & 1))
            atomicAdd(&g_cnt[(int)((const long long*)ei)[E + E - 1]], 1);
    } else {
        const int2* p = (const int2*)((const int*)ei + E);
        if (i < n2) {
            int2 v = p[i];
            atomicAdd(&g_cnt[v.x], 1);
            atomicAdd(&g_cnt[v.y], 1);
        }
        if (i == 0 && (E & 1))
            atomicAdd(&g_cnt[((const int*)ei)[E + E - 1]], 1);
    }
}

// ---------------------------------------------------------------------------
// single-wave decoupled-lookback exclusive scan + dinv.
// Resets g_cnt to zero for the next graph replay (write-after-read).
// ---------------------------------------------------------------------------
__global__ void k_scan_lb(int M) {
    __shared__ int sh[SCB];
    __shared__ int s_off;
    const int t = threadIdx.x;
    const int b = blockIdx.x;
    const int node = b * SCB + t;

    int c = 0;
    if (node < M) {
        c = g_cnt[node];
        g_cnt[node] = 0;                               // self-reset for next replay
        g_dinv[node] = rsqrtf((float)(c + 1));         // +1 self loop
    }

    sh[t] = c;
    __syncthreads();
    for (int o = 1; o < SCB; o <<= 1) {
        int u = (t >= o) ? sh[t - o] : 0;
        __syncthreads();
        sh[t] += u;
        __syncthreads();
    }
    int incl  = sh[t];
    int total = sh[SCB - 1];

    if (t == 0) {
        s_off = 0;
        g_ready[b] = total + 1;     // value+1 doubles as ready flag
    }
    __syncthreads();
    if (t < b) {
        int v;
        while ((v = g_ready[t]) == 0) { }
        atomicAdd(&s_off, v - 1);
    }
    __syncthreads();

    int off = s_off;
    if (node < M) {
        int excl = off + incl - c;
        g_ptr[node]  = excl;
        g_fill[node] = excl;
        if (node == M - 1) g_ptr[M] = off + incl;
    }
}

// fill CSR, 1 edge per thread (max thread-level parallelism for the atomics).
// Block 0 also resets the lookback flags for the next replay.
__global__ void k_fillcsr(const void* __restrict__ ei, int E) {
    if (blockIdx.x == 0 && threadIdx.x < 128) g_ready[threadIdx.x] = 0;
    int is64 = block_probe_is64((const int*)ei);
    int e = blockIdx.x * blockDim.x + threadIdx.x;
    if (e >= E) return;
    int s, d;
    if (is64) {
        const long long* p = (const long long*)ei;
        s = (int)p[e];  d = (int)p[E + e];
    } else {
        const int* p = (const int*)ei;
        s = p[e];       d = p[E + e];
    }
    float c = g_dinv[s] * g_dinv[d];
    int pos = atomicAdd(&g_fill[d], 1);
    g_edge[pos] = make_int2(s, __float_as_int(c));
}

// ---------------------------------------------------------------------------
// tf32 tensor-core GEMM:  Y[M,TN] = op(X)[M,128] * W[128,TN]
// ---------------------------------------------------------------------------
__device__ __forceinline__ unsigned f2tf(float f) {
    unsigned r;
    asm("cvt.rna.tf32.f32 %0, %1;" : "=r"(r) : "f"(f));
    return r;
}

template <int TN, bool PRELU>
__global__ void k_gemm_tf32(const float* __restrict__ Xin, const float* __restrict__ W,
                            const float* __restrict__ bias_in, int M)
{
    constexpr int KC  = 32;
    constexpr int NT  = TN / 8;
    constexpr int PAD = 36;

    const float* __restrict__ X = PRELU ? (const float*)g_agg1 : Xin;
    float* __restrict__ Y       = PRELU ? g_h2 : g_h1;

    __shared__ unsigned xs[64 * PAD];
    __shared__ unsigned wt[TN * PAD];

    const int tid  = threadIdx.x;
    const int lane = tid & 31;
    const int wid  = tid >> 5;
    const int m0   = blockIdx.x * 64;
    const int mw   = wid * 16;

    float acc[NT][4];
#pragma unroll
    for (int t = 0; t < NT; t++) { acc[t][0]=acc[t][1]=acc[t][2]=acc[t][3]=0.f; }

    const int r4 = lane >> 2;
    const int c4 = lane & 3;

    for (int kc = 0; kc < 128; kc += KC) {
#pragma unroll
        for (int i = 0; i < 4; i++) {
            int idx = tid + i * 128;
            int r   = idx >> 3;
            int kv  = (idx & 7) * 4;
            int row = m0 + r;
            float4 v = make_float4(0.f, 0.f, 0.f, 0.f);
            if (row < M) v = *(const float4*)&X[row * 128 + kc + kv];
            if (PRELU) {
                float4 b = *(const float4*)&bias_in[kc + kv];
                v.x = fmaxf(v.x + b.x, 0.f);
                v.y = fmaxf(v.y + b.y, 0.f);
                v.z = fmaxf(v.z + b.z, 0.f);
                v.w = fmaxf(v.w + b.w, 0.f);
            }
            uint4 u = make_uint4(f2tf(v.x), f2tf(v.y), f2tf(v.z), f2tf(v.w));
            *(uint4*)&xs[r * PAD + kv] = u;
        }
#pragma unroll
        for (int i = 0; i < (KC * TN / 4) / 128; i++) {
            int idx = tid + i * 128;
            int kk  = idx / (TN / 4);
            int n4  = (idx % (TN / 4)) * 4;
            float4 v = *(const float4*)&W[(kc + kk) * TN + n4];
            wt[(n4 + 0) * PAD + kk] = f2tf(v.x);
            wt[(n4 + 1) * PAD + kk] = f2tf(v.y);
            wt[(n4 + 2) * PAD + kk] = f2tf(v.z);
            wt[(n4 + 3) * PAD + kk] = f2tf(v.w);
        }
        __syncthreads();

#pragma unroll
        for (int k0 = 0; k0 < KC; k0 += 8) {
            unsigned a0 = xs[(mw + r4    ) * PAD + k0 + c4    ];
            unsigned a1 = xs[(mw + r4 + 8) * PAD + k0 + c4    ];
            unsigned a2 = xs[(mw + r4    ) * PAD + k0 + c4 + 4];
            unsigned a3 = xs[(mw + r4 + 8) * PAD + k0 + c4 + 4];
#pragma unroll
            for (int nt = 0; nt < NT; nt++) {
                unsigned b0 = wt[(nt * 8 + r4) * PAD + k0 + c4    ];
                unsigned b1 = wt[(nt * 8 + r4) * PAD + k0 + c4 + 4];
                asm volatile(
                    "mma.sync.aligned.m16n8k8.row.col.f32.tf32.tf32.f32 "
                    "{%0,%1,%2,%3}, {%4,%5,%6,%7}, {%8,%9}, {%0,%1,%2,%3};"
                    : "+f"(acc[nt][0]), "+f"(acc[nt][1]),
                      "+f"(acc[nt][2]), "+f"(acc[nt][3])
                    : "r"(a0), "r"(a1), "r"(a2), "r"(a3), "r"(b0), "r"(b1));
            }
        }
        __syncthreads();
    }

    const int colb = c4 * 2;
    const int rowa = m0 + mw + r4;
#pragma unroll
    for (int nt = 0; nt < NT; nt++) {
        int n0 = nt * 8 + colb;
        if (rowa < M)
            *(float2*)&Y[rowa * TN + n0] = make_float2(acc[nt][0], acc[nt][1]);
        if (rowa + 8 < M)
            *(float2*)&Y[(rowa + 8) * TN + n0] = make_float2(acc[nt][2], acc[nt][3]);
    }
}

// ---------------------------------------------------------------------------
// Pull aggregation, one warp per node, unroll-4, 4 independent accumulators.
// ---------------------------------------------------------------------------
__global__ void k_gather128(int M)
{
    int w    = (blockIdx.x * blockDim.x + threadIdx.x) >> 5;
    int lane = threadIdx.x & 31;
    if (w >= M) return;
    const float4* __restrict__ H = (const float4*)g_h1;
    int beg = g_ptr[w], end = g_ptr[w + 1];
    float cs = g_dinv[w]; cs *= cs;
    float4 v = H[w * 32 + lane];
    float4 a0 = make_float4(v.x * cs, v.y * cs, v.z * cs, v.w * cs);
    float4 a1 = make_float4(0.f, 0.f, 0.f, 0.f);
    float4 a2 = make_float4(0.f, 0.f, 0.f, 0.f);
    float4 a3 = make_float4(0.f, 0.f, 0.f, 0.f);
    int e = beg;
    for (; e + 4 <= end; e += 4) {
        int2 p0 = g_edge[e];
        int2 p1 = g_edge[e + 1];
        int2 p2 = g_edge[e + 2];
        int2 p3 = g_edge[e + 3];
        float c0 = __int_as_float(p0.y);
        float c1 = __int_as_float(p1.y);
        float c2 = __int_as_float(p2.y);
        float c3 = __int_as_float(p3.y);
        float4 v0 = H[p0.x * 32 + lane];
        float4 v1 = H[p1.x * 32 + lane];
        float4 v2 = H[p2.x * 32 + lane];
        float4 v3 = H[p3.x * 32 + lane];
        a0.x = fmaf(v0.x, c0, a0.x); a0.y = fmaf(v0.y, c0, a0.y);
        a0.z = fmaf(v0.z, c0, a0.z); a0.w = fmaf(v0.w, c0, a0.w);
        a1.x = fmaf(v1.x, c1, a1.x); a1.y = fmaf(v1.y, c1, a1.y);
        a1.z = fmaf(v1.z, c1, a1.z); a1.w = fmaf(v1.w, c1, a1.w);
        a2.x = fmaf(v2.x, c2, a2.x); a2.y = fmaf(v2.y, c2, a2.y);
        a2.z = fmaf(v2.z, c2, a2.z); a2.w = fmaf(v2.w, c2, a2.w);
        a3.x = fmaf(v3.x, c3, a3.x); a3.y = fmaf(v3.y, c3, a3.y);
        a3.z = fmaf(v3.z, c3, a3.z); a3.w = fmaf(v3.w, c3, a3.w);
    }
    for (; e < end; e++) {
        int2 p0 = g_edge[e];
        float c0 = __int_as_float(p0.y);
        float4 v0 = H[p0.x * 32 + lane];
        a0.x = fmaf(v0.x, c0, a0.x); a0.y = fmaf(v0.y, c0, a0.y);
        a0.z = fmaf(v0.z, c0, a0.z); a0.w = fmaf(v0.w, c0, a0.w);
    }
    a0.x += a1.x + a2.x + a3.x;
    a0.y += a1.y + a2.y + a3.y;
    a0.z += a1.z + a2.z + a3.z;
    a0.w += a1.w + a2.w + a3.w;
    ((float4*)g_agg1)[w * 32 + lane] = a0;
}

__global__ void k_gather64(const float* __restrict__ b2, float* __restrict__ outp, int M)
{
    int w    = (blockIdx.x * blockDim.x + threadIdx.x) >> 5;
    int lane = threadIdx.x & 31;
    if (w >= M) return;
    const float2* __restrict__ H = (const float2*)g_h2;
    int beg = g_ptr[w], end = g_ptr[w + 1];
    float cs = g_dinv[w]; cs *= cs;
    float2 v = H[w * 32 + lane];
    float2 bb = ((const float2*)b2)[lane];
    float2 a0 = make_float2(fmaf(v.x, cs, bb.x), fmaf(v.y, cs, bb.y));
    float2 a1 = make_float2(0.f, 0.f);
    float2 a2 = make_float2(0.f, 0.f);
    float2 a3 = make_float2(0.f, 0.f);
    int e = beg;
    for (; e + 4 <= end; e += 4) {
        int2 p0 = g_edge[e];
        int2 p1 = g_edge[e + 1];
        int2 p2 = g_edge[e + 2];
        int2 p3 = g_edge[e + 3];
        float c0 = __int_as_float(p0.y);
        float c1 = __int_as_float(p1.y);
        float c2 = __int_as_float(p2.y);
        float c3 = __int_as_float(p3.y);
        float2 v0 = H[p0.x * 32 + lane];
        float2 v1 = H[p1.x * 32 + lane];
        float2 v2 = H[p2.x * 32 + lane];
        float2 v3 = H[p3.x * 32 + lane];
        a0.x = fmaf(v0.x, c0, a0.x); a0.y = fmaf(v0.y, c0, a0.y);
        a1.x = fmaf(v1.x, c1, a1.x); a1.y = fmaf(v1.y, c1, a1.y);
        a2.x = fmaf(v2.x, c2, a2.x); a2.y = fmaf(v2.y, c2, a2.y);
        a3.x = fmaf(v3.x, c3, a3.x); a3.y = fmaf(v3.y, c3, a3.y);
    }
    for (; e < end; e++) {
        int2 p0 = g_edge[e];
        float c0 = __int_as_float(p0.y);
        float2 v0 = H[p0.x * 32 + lane];
        a0.x = fmaf(v0.x, c0, a0.x); a0.y = fmaf(v0.y, c0, a0.y);
    }
    a0.x += a1.x + a2.x + a3.x;
    a0.y += a1.y + a2.y + a3.y;
    ((float2*)outp)[w * 32 + lane] = a0;
}

// ---------------------------------------------------------------------------
extern "C" void kernel_launch(void* const* d_in, const int* in_sizes, int n_in,
                              void* d_out, int out_size)
{
    const float* x  = (const float*)d_in[0];
    const void*  ei = d_in[1];
    const float* W1 = (const float*)d_in[2];
    const float* b1 = (const float*)d_in[3];
    const float* W2 = (const float*)d_in[4];
    const float* b2 = (const float*)d_in[5];
    float*       out = (float*)d_out;

    const int M = in_sizes[0] / INF;   // 50000
    const int E = in_sizes[1] / 2;     // 800000

    const int T  = 256;
    const int NB = (M + SCB - 1) / SCB;   // <= 98
    const int E2 = (E >> 1) + 1;

    cudaStream_t s1;
    cudaStreamCreateWithFlags(&s1, cudaStreamNonBlocking);
    cudaEvent_t evFork, evJoin;
    cudaEventCreateWithFlags(&evFork, cudaEventDisableTiming);
    cudaEventCreateWithFlags(&evJoin, cudaEventDisableTiming);

    cudaEventRecord(evFork, 0);
    cudaStreamWaitEvent(s1, evFork, 0);

    // chain B (s1): count -> lookback-scan(+dinv, cnt reset) -> fill(+flag reset)
    k_count  <<<(E2 + T - 1) / T, T, 0, s1>>>(ei, E);
    k_scan_lb<<<NB, SCB, 0, s1>>>(M);
    k_fillcsr<<<(E + T - 1) / T, T, 0, s1>>>(ei, E);
    cudaEventRecord(evJoin, s1);

    // chain A (default stream): GEMM1
    k_gemm_tf32<128, false><<<(M + 63) / 64, 128>>>(x, W1, b1, M);

    cudaStreamWaitEvent(0, evJoin, 0);
    k_gather128<<<(M * 32 + T - 1) / T, T>>>(M);
    k_gemm_tf32<64, true><<<(M + 63) / 64, 128>>>(nullptr, W2, b1, M);
    k_gather64<<<(M * 32 + T - 1) / T, T>>>(b2, out, M);
}

// round 15
// speedup vs baseline: 1.1552x; 1.1246x over previous
#include <cuda_runtime.h>
#include <cuda_bf16.h>

// ---------------------------------------------------------------------------
// 2-layer GCN. Compact CSR pull aggregation, tf32 tensor-core GEMMs with
// 128x(TN) block tiles / 32x(TN/2) warp tiles (LDS-per-MMA minimized),
// single-wave lookback scan, self-resetting scratch, fork/join overlap.
// ---------------------------------------------------------------------------

#define NMAX   50048
#define EMAX   800000
#define INF    128
#define OUTF   64
#define SCB    512

__device__ int   g_cnt [NMAX];          // zero at load; re-zeroed by k_scan_lb
__device__ int   g_ptr [NMAX + 1];
__device__ int   g_fill[NMAX];
__device__ volatile int g_ready[128];   // zero at load; re-zeroed by k_fillcsr
__device__ int2  g_edge[EMAX];          // (src, coeff bits)
__device__ float g_dinv[NMAX];
__device__ float g_h1  [NMAX * INF];
__device__ float g_agg1[NMAX * INF];
__device__ float g_h2  [NMAX * OUTF];

// ---------------------------------------------------------------------------
__device__ __forceinline__ int block_probe_is64(const int* __restrict__ w32) {
    __shared__ int s_is64;
    if (threadIdx.x == 0) s_is64 = 1;
    __syncthreads();
    if (threadIdx.x < 256) {
        if (w32[2 * threadIdx.x + 1] != 0) s_is64 = 0;
    }
    __syncthreads();
    return s_is64;
}

// histogram of destinations, 2 edges per thread
__global__ void k_count(const void* __restrict__ ei, int E) {
    int is64 = block_probe_is64((const int*)ei);
    int i  = blockIdx.x * blockDim.x + threadIdx.x;
    int n2 = E >> 1;
    if (is64) {
        const longlong2* p = (const longlong2*)((const long long*)ei + E);
        if (i < n2) {
            longlong2 v = p[i];
            atomicAdd(&g_cnt[(int)v.x], 1);
            atomicAdd(&g_cnt[(int)v.y], 1);
        }
        if (i == 0 && (E & 1))
            atomicAdd(&g_cnt[(int)((const long long*)ei)[E + E - 1]], 1);
    } else {
        const int2* p = (const int2*)((const int*)ei + E);
        if (i < n2) {
            int2 v = p[i];
            atomicAdd(&g_cnt[v.x], 1);
            atomicAdd(&g_cnt[v.y], 1);
        }
        if (i == 0 && (E & 1))
            atomicAdd(&g_cnt[((const int*)ei)[E + E - 1]], 1);
    }
}

// single-wave decoupled-lookback exclusive scan + dinv (+cnt reset)
__global__ void k_scan_lb(int M) {
    __shared__ int sh[SCB];
    __shared__ int s_off;
    const int t = threadIdx.x;
    const int b = blockIdx.x;
    const int node = b * SCB + t;

    int c = 0;
    if (node < M) {
        c = g_cnt[node];
        g_cnt[node] = 0;
        g_dinv[node] = rsqrtf((float)(c + 1));
    }

    sh[t] = c;
    __syncthreads();
    for (int o = 1; o < SCB; o <<= 1) {
        int u = (t >= o) ? sh[t - o] : 0;
        __syncthreads();
        sh[t] += u;
        __syncthreads();
    }
    int incl  = sh[t];
    int total = sh[SCB - 1];

    if (t == 0) {
        s_off = 0;
        g_ready[b] = total + 1;
    }
    __syncthreads();
    if (t < b) {
        int v;
        while ((v = g_ready[t]) == 0) { }
        atomicAdd(&s_off, v - 1);
    }
    __syncthreads();

    int off = s_off;
    if (node < M) {
        int excl = off + incl - c;
        g_ptr[node]  = excl;
        g_fill[node] = excl;
        if (node == M - 1) g_ptr[M] = off + incl;
    }
}

// fill CSR, 1 edge per thread; block 0 resets lookback flags
__global__ void k_fillcsr(const void* __restrict__ ei, int E) {
    if (blockIdx.x == 0 && threadIdx.x < 128) g_ready[threadIdx.x] = 0;
    int is64 = block_probe_is64((const int*)ei);
    int e = blockIdx.x * blockDim.x + threadIdx.x;
    if (e >= E) return;
    int s, d;
    if (is64) {
        const long long* p = (const long long*)ei;
        s = (int)p[e];  d = (int)p[E + e];
    } else {
        const int* p = (const int*)ei;
        s = p[e];       d = p[E + e];
    }
    float c = g_dinv[s] * g_dinv[d];
    int pos = atomicAdd(&g_fill[d], 1);
    g_edge[pos] = make_int2(s, __float_as_int(c));
}

// ---------------------------------------------------------------------------
// tf32 GEMM: Y[M,TN] = op(X)[M,128] * W[128,TN]
// 256 threads / 8 warps; block 128m x TN; warp 32m x TN/2 (4m x 2n warp grid).
// ---------------------------------------------------------------------------
__device__ __forceinline__ unsigned f2tf(float f) {
    unsigned r;
    asm("cvt.rna.tf32.f32 %0, %1;" : "=r"(r) : "f"(f));
    return r;
}

template <int TN, bool PRELU>
__global__ void k_gemm_tf32(const float* __restrict__ Xin, const float* __restrict__ W,
                            const float* __restrict__ bias_in, int M)
{
    constexpr int KC  = 32;
    constexpr int PAD = 36;
    constexpr int NW  = TN / 2;     // n-cols per warp
    constexpr int NT  = NW / 8;     // n-frags per warp (8 or 4)

    const float* __restrict__ X = PRELU ? (const float*)g_agg1 : Xin;
    float* __restrict__ Y       = PRELU ? g_h2 : g_h1;

    __shared__ unsigned xs[128 * PAD];
    __shared__ unsigned wt[TN * PAD];

    const int tid    = threadIdx.x;
    const int lane   = tid & 31;
    const int wid    = tid >> 5;
    const int warp_m = wid & 3;
    const int warp_n = wid >> 2;
    const int m0     = blockIdx.x * 128;
    const int mw     = warp_m * 32;
    const int nb     = warp_n * NW;

    float acc[2][NT][4];
#pragma unroll
    for (int mf = 0; mf < 2; mf++)
#pragma unroll
        for (int nt = 0; nt < NT; nt++) {
            acc[mf][nt][0]=acc[mf][nt][1]=acc[mf][nt][2]=acc[mf][nt][3]=0.f;
        }

    const int r4 = lane >> 2;
    const int c4 = lane & 3;

    for (int kc = 0; kc < 128; kc += KC) {
        // X tile: 128 rows x KC floats = 1024 float4, 256 threads x 4
#pragma unroll
        for (int i = 0; i < 4; i++) {
            int idx = tid + i * 256;
            int r   = idx >> 3;
            int kv  = (idx & 7) * 4;
            int row = m0 + r;
            float4 v = make_float4(0.f, 0.f, 0.f, 0.f);
            if (row < M) v = *(const float4*)&X[row * 128 + kc + kv];
            if (PRELU) {
                float4 b = *(const float4*)&bias_in[kc + kv];
                v.x = fmaxf(v.x + b.x, 0.f);
                v.y = fmaxf(v.y + b.y, 0.f);
                v.z = fmaxf(v.z + b.z, 0.f);
                v.w = fmaxf(v.w + b.w, 0.f);
            }
            uint4 u = make_uint4(f2tf(v.x), f2tf(v.y), f2tf(v.z), f2tf(v.w));
            *(uint4*)&xs[r * PAD + kv] = u;
        }
        // W chunk transposed: KC x TN floats
#pragma unroll
        for (int i = 0; i < (KC * TN / 4) / 256; i++) {
            int idx = tid + i * 256;
            int kk  = idx / (TN / 4);
            int n4  = (idx % (TN / 4)) * 4;
            float4 v = *(const float4*)&W[(kc + kk) * TN + n4];
            wt[(n4 + 0) * PAD + kk] = f2tf(v.x);
            wt[(n4 + 1) * PAD + kk] = f2tf(v.y);
            wt[(n4 + 2) * PAD + kk] = f2tf(v.z);
            wt[(n4 + 3) * PAD + kk] = f2tf(v.w);
        }
        __syncthreads();

#pragma unroll
        for (int k0 = 0; k0 < KC; k0 += 8) {
            unsigned a[2][4];
#pragma unroll
            for (int mf = 0; mf < 2; mf++) {
                int base = mw + mf * 16;
                a[mf][0] = xs[(base + r4    ) * PAD + k0 + c4    ];
                a[mf][1] = xs[(base + r4 + 8) * PAD + k0 + c4    ];
                a[mf][2] = xs[(base + r4    ) * PAD + k0 + c4 + 4];
                a[mf][3] = xs[(base + r4 + 8) * PAD + k0 + c4 + 4];
            }
#pragma unroll
            for (int nt = 0; nt < NT; nt++) {
                unsigned b0 = wt[(nb + nt * 8 + r4) * PAD + k0 + c4    ];
                unsigned b1 = wt[(nb + nt * 8 + r4) * PAD + k0 + c4 + 4];
#pragma unroll
                for (int mf = 0; mf < 2; mf++) {
                    asm volatile(
                        "mma.sync.aligned.m16n8k8.row.col.f32.tf32.tf32.f32 "
                        "{%0,%1,%2,%3}, {%4,%5,%6,%7}, {%8,%9}, {%0,%1,%2,%3};"
                        : "+f"(acc[mf][nt][0]), "+f"(acc[mf][nt][1]),
                          "+f"(acc[mf][nt][2]), "+f"(acc[mf][nt][3])
                        : "r"(a[mf][0]), "r"(a[mf][1]), "r"(a[mf][2]), "r"(a[mf][3]),
                          "r"(b0), "r"(b1));
                }
            }
        }
        __syncthreads();
    }

    const int colb = c4 * 2;
#pragma unroll
    for (int mf = 0; mf < 2; mf++) {
        const int rowa = m0 + mw + mf * 16 + r4;
#pragma unroll
        for (int nt = 0; nt < NT; nt++) {
            int n0 = nb + nt * 8 + colb;
            if (rowa < M)
                *(float2*)&Y[rowa * TN + n0] =
                    make_float2(acc[mf][nt][0], acc[mf][nt][1]);
            if (rowa + 8 < M)
                *(float2*)&Y[(rowa + 8) * TN + n0] =
                    make_float2(acc[mf][nt][2], acc[mf][nt][3]);
        }
    }
}

// ---------------------------------------------------------------------------
// Pull aggregation, one warp per node, unroll-4, 4 independent accumulators.
// ---------------------------------------------------------------------------
__global__ void k_gather128(int M)
{
    int w    = (blockIdx.x * blockDim.x + threadIdx.x) >> 5;
    int lane = threadIdx.x & 31;
    if (w >= M) return;
    const float4* __restrict__ H = (const float4*)g_h1;
    int beg = g_ptr[w], end = g_ptr[w + 1];
    float cs = g_dinv[w]; cs *= cs;
    float4 v = H[w * 32 + lane];
    float4 a0 = make_float4(v.x * cs, v.y * cs, v.z * cs, v.w * cs);
    float4 a1 = make_float4(0.f, 0.f, 0.f, 0.f);
    float4 a2 = make_float4(0.f, 0.f, 0.f, 0.f);
    float4 a3 = make_float4(0.f, 0.f, 0.f, 0.f);
    int e = beg;
    for (; e + 4 <= end; e += 4) {
        int2 p0 = g_edge[e];
        int2 p1 = g_edge[e + 1];
        int2 p2 = g_edge[e + 2];
        int2 p3 = g_edge[e + 3];
        float c0 = __int_as_float(p0.y);
        float c1 = __int_as_float(p1.y);
        float c2 = __int_as_float(p2.y);
        float c3 = __int_as_float(p3.y);
        float4 v0 = H[p0.x * 32 + lane];
        float4 v1 = H[p1.x * 32 + lane];
        float4 v2 = H[p2.x * 32 + lane];
        float4 v3 = H[p3.x * 32 + lane];
        a0.x = fmaf(v0.x, c0, a0.x); a0.y = fmaf(v0.y, c0, a0.y);
        a0.z = fmaf(v0.z, c0, a0.z); a0.w = fmaf(v0.w, c0, a0.w);
        a1.x = fmaf(v1.x, c1, a1.x); a1.y = fmaf(v1.y, c1, a1.y);
        a1.z = fmaf(v1.z, c1, a1.z); a1.w = fmaf(v1.w, c1, a1.w);
        a2.x = fmaf(v2.x, c2, a2.x); a2.y = fmaf(v2.y, c2, a2.y);
        a2.z = fmaf(v2.z, c2, a2.z); a2.w = fmaf(v2.w, c2, a2.w);
        a3.x = fmaf(v3.x, c3, a3.x); a3.y = fmaf(v3.y, c3, a3.y);
        a3.z = fmaf(v3.z, c3, a3.z); a3.w = fmaf(v3.w, c3, a3.w);
    }
    for (; e < end; e++) {
        int2 p0 = g_edge[e];
        float c0 = __int_as_float(p0.y);
        float4 v0 = H[p0.x * 32 + lane];
        a0.x = fmaf(v0.x, c0, a0.x); a0.y = fmaf(v0.y, c0, a0.y);
        a0.z = fmaf(v0.z, c0, a0.z); a0.w = fmaf(v0.w, c0, a0.w);
    }
    a0.x += a1.x + a2.x + a3.x;
    a0.y += a1.y + a2.y + a3.y;
    a0.z += a1.z + a2.z + a3.z;
    a0.w += a1.w + a2.w + a3.w;
    ((float4*)g_agg1)[w * 32 + lane] = a0;
}

__global__ void k_gather64(const float* __restrict__ b2, float* __restrict__ outp, int M)
{
    int w    = (blockIdx.x * blockDim.x + threadIdx.x) >> 5;
    int lane = threadIdx.x & 31;
    if (w >= M) return;
    const float2* __restrict__ H = (const float2*)g_h2;
    int beg = g_ptr[w], end = g_ptr[w + 1];
    float cs = g_dinv[w]; cs *= cs;
    float2 v = H[w * 32 + lane];
    float2 bb = ((const float2*)b2)[lane];
    float2 a0 = make_float2(fmaf(v.x, cs, bb.x), fmaf(v.y, cs, bb.y));
    float2 a1 = make_float2(0.f, 0.f);
    float2 a2 = make_float2(0.f, 0.f);
    float2 a3 = make_float2(0.f, 0.f);
    int e = beg;
    for (; e + 4 <= end; e += 4) {
        int2 p0 = g_edge[e];
        int2 p1 = g_edge[e + 1];
        int2 p2 = g_edge[e + 2];
        int2 p3 = g_edge[e + 3];
        float c0 = __int_as_float(p0.y);
        float c1 = __int_as_float(p1.y);
        float c2 = __int_as_float(p2.y);
        float c3 = __int_as_float(p3.y);
        float2 v0 = H[p0.x * 32 + lane];
        float2 v1 = H[p1.x * 32 + lane];
        float2 v2 = H[p2.x * 32 + lane];
        float2 v3 = H[p3.x * 32 + lane];
        a0.x = fmaf(v0.x, c0, a0.x); a0.y = fmaf(v0.y, c0, a0.y);
        a1.x = fmaf(v1.x, c1, a1.x); a1.y = fmaf(v1.y, c1, a1.y);
        a2.x = fmaf(v2.x, c2, a2.x); a2.y = fmaf(v2.y, c2, a2.y);
        a3.x = fmaf(v3.x, c3, a3.x); a3.y = fmaf(v3.y, c3, a3.y);
    }
    for (; e < end; e++) {
        int2 p0 = g_edge[e];
        float c0 = __int_as_float(p0.y);
        float2 v0 = H[p0.x * 32 + lane];
        a0.x = fmaf(v0.x, c0, a0.x); a0.y = fmaf(v0.y, c0, a0.y);
    }
    a0.x += a1.x + a2.x + a3.x;
    a0.y += a1.y + a2.y + a3.y;
    ((float2*)outp)[w * 32 + lane] = a0;
}

// ---------------------------------------------------------------------------
extern "C" void kernel_launch(void* const* d_in, const int* in_sizes, int n_in,
                              void* d_out, int out_size)
{
    const float* x  = (const float*)d_in[0];
    const void*  ei = d_in[1];
    const float* W1 = (const float*)d_in[2];
    const float* b1 = (const float*)d_in[3];
    const float* W2 = (const float*)d_in[4];
    const float* b2 = (const float*)d_in[5];
    float*       out = (float*)d_out;

    const int M = in_sizes[0] / INF;   // 50000
    const int E = in_sizes[1] / 2;     // 800000

    const int T  = 256;
    const int NB = (M + SCB - 1) / SCB;
    const int E2 = (E >> 1) + 1;

    cudaStream_t s1;
    cudaStreamCreateWithFlags(&s1, cudaStreamNonBlocking);
    cudaEvent_t evFork, evJoin;
    cudaEventCreateWithFlags(&evFork, cudaEventDisableTiming);
    cudaEventCreateWithFlags(&evJoin, cudaEventDisableTiming);

    cudaEventRecord(evFork, 0);
    cudaStreamWaitEvent(s1, evFork, 0);

    // chain B (s1): count -> lookback-scan(+dinv, cnt reset) -> fill(+flag reset)
    k_count  <<<(E2 + T - 1) / T, T, 0, s1>>>(ei, E);
    k_scan_lb<<<NB, SCB, 0, s1>>>(M);
    k_fillcsr<<<(E + T - 1) / T, T, 0, s1>>>(ei, E);
    cudaEventRecord(evJoin, s1);

    // chain A (default stream): GEMM1 (128-row tiles, 256 threads)
    k_gemm_tf32<128, false><<<(M + 127) / 128, 256>>>(x, W1, b1, M);

    cudaStreamWaitEvent(0, evJoin, 0);
    k_gather128<<<(M * 32 + T - 1) / T, T>>>(M);
    k_gemm_tf32<64, true><<<(M + 127) / 128, 256>>>(nullptr, W2, b1, M);
    k_gather64<<<(M * 32 + T - 1) / T, T>>>(b2, out, M);
}

// round 16
// speedup vs baseline: 1.1614x; 1.0053x over previous
#include <cuda_runtime.h>
#include <cuda_bf16.h>

// ---------------------------------------------------------------------------
// 2-layer GCN. Compact CSR pull aggregation, tf32 tensor-core GEMMs
// (128xTN block / 32x(TN/2) warp tiles, ldmatrix.x4 fragment loads),
// single-wave lookback scan, self-resetting scratch, fork/join overlap.
// ---------------------------------------------------------------------------

#define NMAX   50048
#define EMAX   800000
#define INF    128
#define OUTF   64
#define SCB    512

__device__ int   g_cnt [NMAX];          // zero at load; re-zeroed by k_scan_lb
__device__ int   g_ptr [NMAX + 1];
__device__ int   g_fill[NMAX];
__device__ volatile int g_ready[128];   // zero at load; re-zeroed by k_fillcsr
__device__ int2  g_edge[EMAX];          // (src, coeff bits)
__device__ float g_dinv[NMAX];
__device__ float g_h1  [NMAX * INF];
__device__ float g_agg1[NMAX * INF];
__device__ float g_h2  [NMAX * OUTF];

// ---------------------------------------------------------------------------
__device__ __forceinline__ int block_probe_is64(const int* __restrict__ w32) {
    __shared__ int s_is64;
    if (threadIdx.x == 0) s_is64 = 1;
    __syncthreads();
    if (threadIdx.x < 256) {
        if (w32[2 * threadIdx.x + 1] != 0) s_is64 = 0;
    }
    __syncthreads();
    return s_is64;
}

// histogram of destinations, 2 edges per thread
__global__ void k_count(const void* __restrict__ ei, int E) {
    int is64 = block_probe_is64((const int*)ei);
    int i  = blockIdx.x * blockDim.x + threadIdx.x;
    int n2 = E >> 1;
    if (is64) {
        const longlong2* p = (const longlong2*)((const long long*)ei + E);
        if (i < n2) {
            longlong2 v = p[i];
            atomicAdd(&g_cnt[(int)v.x], 1);
            atomicAdd(&g_cnt[(int)v.y], 1);
        }
        if (i == 0 && (E & 1))
            atomicAdd(&g_cnt[(int)((const long long*)ei)[E + E - 1]], 1);
    } else {
        const int2* p = (const int2*)((const int*)ei + E);
        if (i < n2) {
            int2 v = p[i];
            atomicAdd(&g_cnt[v.x], 1);
            atomicAdd(&g_cnt[v.y], 1);
        }
        if (i == 0 && (E & 1))
            atomicAdd(&g_cnt[((const int*)ei)[E + E - 1]], 1);
    }
}

// single-wave decoupled-lookback exclusive scan + dinv (+cnt reset)
__global__ void k_scan_lb(int M) {
    __shared__ int sh[SCB];
    __shared__ int s_off;
    const int t = threadIdx.x;
    const int b = blockIdx.x;
    const int node = b * SCB + t;

    int c = 0;
    if (node < M) {
        c = g_cnt[node];
        g_cnt[node] = 0;
        g_dinv[node] = rsqrtf((float)(c + 1));
    }

    sh[t] = c;
    __syncthreads();
    for (int o = 1; o < SCB; o <<= 1) {
        int u = (t >= o) ? sh[t - o] : 0;
        __syncthreads();
        sh[t] += u;
        __syncthreads();
    }
    int incl  = sh[t];
    int total = sh[SCB - 1];

    if (t == 0) {
        s_off = 0;
        g_ready[b] = total + 1;
    }
    __syncthreads();
    if (t < b) {
        int v;
        while ((v = g_ready[t]) == 0) { }
        atomicAdd(&s_off, v - 1);
    }
    __syncthreads();

    int off = s_off;
    if (node < M) {
        int excl = off + incl - c;
        g_ptr[node]  = excl;
        g_fill[node] = excl;
        if (node == M - 1) g_ptr[M] = off + incl;
    }
}

// fill CSR, 1 edge per thread; block 0 resets lookback flags
__global__ void k_fillcsr(const void* __restrict__ ei, int E) {
    if (blockIdx.x == 0 && threadIdx.x < 128) g_ready[threadIdx.x] = 0;
    int is64 = block_probe_is64((const int*)ei);
    int e = blockIdx.x * blockDim.x + threadIdx.x;
    if (e >= E) return;
    int s, d;
    if (is64) {
        const long long* p = (const long long*)ei;
        s = (int)p[e];  d = (int)p[E + e];
    } else {
        const int* p = (const int*)ei;
        s = p[e];       d = p[E + e];
    }
    float c = g_dinv[s] * g_dinv[d];
    int pos = atomicAdd(&g_fill[d], 1);
    g_edge[pos] = make_int2(s, __float_as_int(c));
}

// ---------------------------------------------------------------------------
// tf32 GEMM: Y[M,TN] = op(X)[M,128] * W[128,TN]
// 256 threads / 8 warps; block 128m x TN; warp 32m x TN/2.
// Fragments loaded via ldmatrix.m8n8.x4 (tf32 8x4-b32 tile == b16 8x16B tile).
// ---------------------------------------------------------------------------
__device__ __forceinline__ unsigned f2tf(float f) {
    unsigned r;
    asm("cvt.rna.tf32.f32 %0, %1;" : "=r"(r) : "f"(f));
    return r;
}

__device__ __forceinline__ void ldsm4(unsigned& r0, unsigned& r1,
                                      unsigned& r2, unsigned& r3, unsigned addr) {
    asm volatile("ldmatrix.sync.aligned.m8n8.x4.shared.b16 {%0,%1,%2,%3}, [%4];"
                 : "=r"(r0), "=r"(r1), "=r"(r2), "=r"(r3) : "r"(addr));
}

template <int TN, bool PRELU>
__global__ void k_gemm_tf32(const float* __restrict__ Xin, const float* __restrict__ W,
                            const float* __restrict__ bias_in, int M)
{
    constexpr int KC  = 32;
    constexpr int PAD = 36;
    constexpr int NW  = TN / 2;     // n-cols per warp
    constexpr int NT  = NW / 8;     // n-frags per warp (8 or 4)
    constexpr int NP  = NT / 2;     // b-ldmatrix pairs (4 or 2)

    const float* __restrict__ X = PRELU ? (const float*)g_agg1 : Xin;
    float* __restrict__ Y       = PRELU ? g_h2 : g_h1;

    __shared__ unsigned xs[128 * PAD];
    __shared__ unsigned wt[TN * PAD];

    const int tid    = threadIdx.x;
    const int lane   = tid & 31;
    const int wid    = tid >> 5;
    const int warp_m = wid & 3;
    const int warp_n = wid >> 2;
    const int m0     = blockIdx.x * 128;
    const int mw     = warp_m * 32;
    const int nb     = warp_n * NW;

    float acc[2][NT][4];
#pragma unroll
    for (int mf = 0; mf < 2; mf++)
#pragma unroll
        for (int nt = 0; nt < NT; nt++) {
            acc[mf][nt][0]=acc[mf][nt][1]=acc[mf][nt][2]=acc[mf][nt][3]=0.f;
        }

    // ldmatrix per-thread base addresses
    const int grp = lane >> 3;          // matrix index 0..3
    const int tr  = lane & 7;           // row within matrix
    unsigned xs_base = (unsigned)__cvta_generic_to_shared(xs);
    unsigned wt_base = (unsigned)__cvta_generic_to_shared(wt);
    // A matrices: grp&1 -> +8 rows, grp>>1 -> +4 cols  (r0..r3 = a0..a3)
    unsigned a_addr[2];
#pragma unroll
    for (int mf = 0; mf < 2; mf++) {
        int row = mw + mf * 16 + (grp & 1) * 8 + tr;
        int col = (grp >> 1) * 4;
        a_addr[mf] = xs_base + (row * PAD + col) * 4;
    }
    // B matrices: grp>>1 -> nt within pair, grp&1 -> +4 cols
    // (r0,r1 = b0,b1 of nt=2j ; r2,r3 = b0,b1 of nt=2j+1)
    unsigned b_addr[NP];
#pragma unroll
    for (int j = 0; j < NP; j++) {
        int row = nb + (2 * j + (grp >> 1)) * 8 + tr;
        int col = (grp & 1) * 4;
        b_addr[j] = wt_base + (row * PAD + col) * 4;
    }

    const int r4 = lane >> 2;
    const int c4 = lane & 3;

    for (int kc = 0; kc < 128; kc += KC) {
        // X tile: 128 rows x KC floats = 1024 float4, 256 threads x 4
#pragma unroll
        for (int i = 0; i < 4; i++) {
            int idx = tid + i * 256;
            int r   = idx >> 3;
            int kv  = (idx & 7) * 4;
            int row = m0 + r;
            float4 v = make_float4(0.f, 0.f, 0.f, 0.f);
            if (row < M) v = *(const float4*)&X[row * 128 + kc + kv];
            if (PRELU) {
                float4 b = *(const float4*)&bias_in[kc + kv];
                v.x = fmaxf(v.x + b.x, 0.f);
                v.y = fmaxf(v.y + b.y, 0.f);
                v.z = fmaxf(v.z + b.z, 0.f);
                v.w = fmaxf(v.w + b.w, 0.f);
            }
            uint4 u = make_uint4(f2tf(v.x), f2tf(v.y), f2tf(v.z), f2tf(v.w));
            *(uint4*)&xs[r * PAD + kv] = u;
        }
        // W chunk transposed: KC x TN floats
#pragma unroll
        for (int i = 0; i < (KC * TN / 4) / 256; i++) {
            int idx = tid + i * 256;
            int kk  = idx / (TN / 4);
            int n4  = (idx % (TN / 4)) * 4;
            float4 v = *(const float4*)&W[(kc + kk) * TN + n4];
            wt[(n4 + 0) * PAD + kk] = f2tf(v.x);
            wt[(n4 + 1) * PAD + kk] = f2tf(v.y);
            wt[(n4 + 2) * PAD + kk] = f2tf(v.z);
            wt[(n4 + 3) * PAD + kk] = f2tf(v.w);
        }
        __syncthreads();

#pragma unroll
        for (int k0 = 0; k0 < KC; k0 += 8) {
            unsigned a[2][4];
            ldsm4(a[0][0], a[0][1], a[0][2], a[0][3], a_addr[0] + k0 * 4);
            ldsm4(a[1][0], a[1][1], a[1][2], a[1][3], a_addr[1] + k0 * 4);
#pragma unroll
            for (int j = 0; j < NP; j++) {
                unsigned b0, b1, b2, b3;
                ldsm4(b0, b1, b2, b3, b_addr[j] + k0 * 4);
#pragma unroll
                for (int mf = 0; mf < 2; mf++) {
                    asm volatile(
                        "mma.sync.aligned.m16n8k8.row.col.f32.tf32.tf32.f32 "
                        "{%0,%1,%2,%3}, {%4,%5,%6,%7}, {%8,%9}, {%0,%1,%2,%3};"
                        : "+f"(acc[mf][2*j][0]), "+f"(acc[mf][2*j][1]),
                          "+f"(acc[mf][2*j][2]), "+f"(acc[mf][2*j][3])
                        : "r"(a[mf][0]), "r"(a[mf][1]), "r"(a[mf][2]), "r"(a[mf][3]),
                          "r"(b0), "r"(b1));
                    asm volatile(
                        "mma.sync.aligned.m16n8k8.row.col.f32.tf32.tf32.f32 "
                        "{%0,%1,%2,%3}, {%4,%5,%6,%7}, {%8,%9}, {%0,%1,%2,%3};"
                        : "+f"(acc[mf][2*j+1][0]), "+f"(acc[mf][2*j+1][1]),
                          "+f"(acc[mf][2*j+1][2]), "+f"(acc[mf][2*j+1][3])
                        : "r"(a[mf][0]), "r"(a[mf][1]), "r"(a[mf][2]), "r"(a[mf][3]),
                          "r"(b2), "r"(b3));
                }
            }
        }
        __syncthreads();
    }

    const int colb = c4 * 2;
#pragma unroll
    for (int mf = 0; mf < 2; mf++) {
        const int rowa = m0 + mw + mf * 16 + r4;
#pragma unroll
        for (int nt = 0; nt < NT; nt++) {
            int n0 = nb + nt * 8 + colb;
            if (rowa < M)
                *(float2*)&Y[rowa * TN + n0] =
                    make_float2(acc[mf][nt][0], acc[mf][nt][1]);
            if (rowa + 8 < M)
                *(float2*)&Y[(rowa + 8) * TN + n0] =
                    make_float2(acc[mf][nt][2], acc[mf][nt][3]);
        }
    }
}

// ---------------------------------------------------------------------------
// Pull aggregation, one warp per node, unroll-4, 4 independent accumulators.
// ---------------------------------------------------------------------------
__global__ void k_gather128(int M)
{
    int w    = (blockIdx.x * blockDim.x + threadIdx.x) >> 5;
    int lane = threadIdx.x & 31;
    if (w >= M) return;
    const float4* __restrict__ H = (const float4*)g_h1;
    int beg = g_ptr[w], end = g_ptr[w + 1];
    float cs = g_dinv[w]; cs *= cs;
    float4 v = H[w * 32 + lane];
    float4 a0 = make_float4(v.x * cs, v.y * cs, v.z * cs, v.w * cs);
    float4 a1 = make_float4(0.f, 0.f, 0.f, 0.f);
    float4 a2 = make_float4(0.f, 0.f, 0.f, 0.f);
    float4 a3 = make_float4(0.f, 0.f, 0.f, 0.f);
    int e = beg;
    for (; e + 4 <= end; e += 4) {
        int2 p0 = g_edge[e];
        int2 p1 = g_edge[e + 1];
        int2 p2 = g_edge[e + 2];
        int2 p3 = g_edge[e + 3];
        float c0 = __int_as_float(p0.y);
        float c1 = __int_as_float(p1.y);
        float c2 = __int_as_float(p2.y);
        float c3 = __int_as_float(p3.y);
        float4 v0 = H[p0.x * 32 + lane];
        float4 v1 = H[p1.x * 32 + lane];
        float4 v2 = H[p2.x * 32 + lane];
        float4 v3 = H[p3.x * 32 + lane];
        a0.x = fmaf(v0.x, c0, a0.x); a0.y = fmaf(v0.y, c0, a0.y);
        a0.z = fmaf(v0.z, c0, a0.z); a0.w = fmaf(v0.w, c0, a0.w);
        a1.x = fmaf(v1.x, c1, a1.x); a1.y = fmaf(v1.y, c1, a1.y);
        a1.z = fmaf(v1.z, c1, a1.z); a1.w = fmaf(v1.w, c1, a1.w);
        a2.x = fmaf(v2.x, c2, a2.x); a2.y = fmaf(v2.y, c2, a2.y);
        a2.z = fmaf(v2.z, c2, a2.z); a2.w = fmaf(v2.w, c2, a2.w);
        a3.x = fmaf(v3.x, c3, a3.x); a3.y = fmaf(v3.y, c3, a3.y);
        a3.z = fmaf(v3.z, c3, a3.z); a3.w = fmaf(v3.w, c3, a3.w);
    }
    for (; e < end; e++) {
        int2 p0 = g_edge[e];
        float c0 = __int_as_float(p0.y);
        float4 v0 = H[p0.x * 32 + lane];
        a0.x = fmaf(v0.x, c0, a0.x); a0.y = fmaf(v0.y, c0, a0.y);
        a0.z = fmaf(v0.z, c0, a0.z); a0.w = fmaf(v0.w, c0, a0.w);
    }
    a0.x += a1.x + a2.x + a3.x;
    a0.y += a1.y + a2.y + a3.y;
    a0.z += a1.z + a2.z + a3.z;
    a0.w += a1.w + a2.w + a3.w;
    ((float4*)g_agg1)[w * 32 + lane] = a0;
}

__global__ void k_gather64(const float* __restrict__ b2, float* __restrict__ outp, int M)
{
    int w    = (blockIdx.x * blockDim.x + threadIdx.x) >> 5;
    int lane = threadIdx.x & 31;
    if (w >= M) return;
    const float2* __restrict__ H = (const float2*)g_h2;
    int beg = g_ptr[w], end = g_ptr[w + 1];
    float cs = g_dinv[w]; cs *= cs;
    float2 v = H[w * 32 + lane];
    float2 bb = ((const float2*)b2)[lane];
    float2 a0 = make_float2(fmaf(v.x, cs, bb.x), fmaf(v.y, cs, bb.y));
    float2 a1 = make_float2(0.f, 0.f);
    float2 a2 = make_float2(0.f, 0.f);
    float2 a3 = make_float2(0.f, 0.f);
    int e = beg;
    for (; e + 4 <= end; e += 4) {
        int2 p0 = g_edge[e];
        int2 p1 = g_edge[e + 1];
        int2 p2 = g_edge[e + 2];
        int2 p3 = g_edge[e + 3];
        float c0 = __int_as_float(p0.y);
        float c1 = __int_as_float(p1.y);
        float c2 = __int_as_float(p2.y);
        float c3 = __int_as_float(p3.y);
        float2 v0 = H[p0.x * 32 + lane];
        float2 v1 = H[p1.x * 32 + lane];
        float2 v2 = H[p2.x * 32 + lane];
        float2 v3 = H[p3.x * 32 + lane];
        a0.x = fmaf(v0.x, c0, a0.x); a0.y = fmaf(v0.y, c0, a0.y);
        a1.x = fmaf(v1.x, c1, a1.x); a1.y = fmaf(v1.y, c1, a1.y);
        a2.x = fmaf(v2.x, c2, a2.x); a2.y = fmaf(v2.y, c2, a2.y);
        a3.x = fmaf(v3.x, c3, a3.x); a3.y = fmaf(v3.y, c3, a3.y);
    }
    for (; e < end; e++) {
        int2 p0 = g_edge[e];
        float c0 = __int_as_float(p0.y);
        float2 v0 = H[p0.x * 32 + lane];
        a0.x = fmaf(v0.x, c0, a0.x); a0.y = fmaf(v0.y, c0, a0.y);
    }
    a0.x += a1.x + a2.x + a3.x;
    a0.y += a1.y + a2.y + a3.y;
    ((float2*)outp)[w * 32 + lane] = a0;
}

// ---------------------------------------------------------------------------
extern "C" void kernel_launch(void* const* d_in, const int* in_sizes, int n_in,
                              void* d_out, int out_size)
{
    const float* x  = (const float*)d_in[0];
    const void*  ei = d_in[1];
    const float* W1 = (const float*)d_in[2];
    const float* b1 = (const float*)d_in[3];
    const float* W2 = (const float*)d_in[4];
    const float* b2 = (const float*)d_in[5];
    float*       out = (float*)d_out;

    const int M = in_sizes[0] / INF;   // 50000
    const int E = in_sizes[1] / 2;     // 800000

    const int T  = 256;
    const int NB = (M + SCB - 1) / SCB;
    const int E2 = (E >> 1) + 1;

    cudaStream_t s1;
    cudaStreamCreateWithFlags(&s1, cudaStreamNonBlocking);
    cudaEvent_t evFork, evJoin;
    cudaEventCreateWithFlags(&evFork, cudaEventDisableTiming);
    cudaEventCreateWithFlags(&evJoin, cudaEventDisableTiming);

    cudaEventRecord(evFork, 0);
    cudaStreamWaitEvent(s1, evFork, 0);

    // chain B (s1): count -> lookback-scan(+dinv, cnt reset) -> fill(+flag reset)
    k_count  <<<(E2 + T - 1) / T, T, 0, s1>>>(ei, E);
    k_scan_lb<<<NB, SCB, 0, s1>>>(M);
    k_fillcsr<<<(E + T - 1) / T, T, 0, s1>>>(ei, E);
    cudaEventRecord(evJoin, s1);

    // chain A (default stream): GEMM1 (128-row tiles, 256 threads)
    k_gemm_tf32<128, false><<<(M + 127) / 128, 256>>>(x, W1, b1, M);

    cudaStreamWaitEvent(0, evJoin, 0);
    k_gather128<<<(M * 32 + T - 1) / T, T>>>(M);
    k_gemm_tf32<64, true><<<(M + 127) / 128, 256>>>(nullptr, W2, b1, M);
    k_gather64<<<(M * 32 + T - 1) / T, T>>>(b2, out, M);
}